// round 6
// baseline (speedup 1.0000x reference)
#include <cuda_runtime.h>
#include <cstdint>

#define NUM_E      5
#define NTOK       (16 * 2048)
#define OUTF       512
#define MAXF       128
#define BM         128
#define BN         128
#define MAX_ROWS   (NTOK + NUM_E * BM)
#define MAX_MTILES (MAX_ROWS / BM)
#define SMEM_BYTES ((BM + BN) * 132 * 4)

// ---------------- scratch (static device globals; zero-initialized at load) ---------------
__device__ int g_counts[NUM_E];        // invariant: zero at entry of k_count (reset by k_offsets)
__device__ int g_offsets[NUM_E + 1];   // 128-aligned exclusive scan of counts
__device__ int g_slot[NTOK];           // slot of token within its expert bucket
__device__ int g_rows[MAX_ROWS];       // gathered row -> token id (-1 = padding)

// in_feat_size may be int32 or int64 depending on jax x64 config. Values are in
// {8,16,32,64,128} (never 0), little-endian: if int64, word[1] (high half of elem 0) is 0.
__device__ __forceinline__ int expert_of(const int* __restrict__ feat, int t) {
    int is64 = (feat[1] == 0) ? 1 : 0;
    int v = feat[is64 ? (t << 1) : t];
    return __ffs(v) - 4;   // 8->0, 16->1, 32->2, 64->3, 128->4
}

__global__ void k_count(const int* __restrict__ feat) {
    int t = blockIdx.x * blockDim.x + threadIdx.x;
    if (t >= NTOK) return;
    int e = expert_of(feat, t);
    g_slot[t] = atomicAdd(&g_counts[e], 1);
}

__global__ void k_offsets() {
    if (threadIdx.x == 0) {
        int acc = 0;
        for (int e = 0; e < NUM_E; e++) {
            g_offsets[e] = acc;
            acc += (g_counts[e] + BM - 1) / BM * BM;   // pad each expert to BM rows
        }
        g_offsets[NUM_E] = acc;
    }
    __syncthreads();
    // mark padding rows
    for (int e = 0; e < NUM_E; e++) {
        int s  = g_offsets[e] + g_counts[e];
        int en = g_offsets[e + 1];
        for (int i = s + (int)threadIdx.x; i < en; i += blockDim.x) g_rows[i] = -1;
    }
    __syncthreads();
    // reset counts so the next graph replay sees zeros
    if (threadIdx.x < NUM_E) g_counts[threadIdx.x] = 0;
}

__global__ void k_scatter(const int* __restrict__ feat) {
    int t = blockIdx.x * blockDim.x + threadIdx.x;
    if (t >= NTOK) return;
    int e = expert_of(feat, t);
    g_rows[g_offsets[e] + g_slot[t]] = t;
}

// ---------------- 3xTF32 GEMM ----------------
__device__ __forceinline__ void split_tf32(float f, uint32_t& hi, uint32_t& lo) {
    asm("cvt.rna.tf32.f32 %0, %1;" : "=r"(hi) : "f"(f));
    float lf = f - __uint_as_float(hi);                 // exact in fp32
    asm("cvt.rna.tf32.f32 %0, %1;" : "=r"(lo) : "f"(lf));
}

__device__ __forceinline__ void mma8(float* c, const uint32_t* a, const uint32_t* b) {
    asm volatile(
        "mma.sync.aligned.m16n8k8.row.col.f32.tf32.tf32.f32 "
        "{%0,%1,%2,%3}, {%4,%5,%6,%7}, {%8,%9}, {%0,%1,%2,%3};\n"
        : "+f"(c[0]), "+f"(c[1]), "+f"(c[2]), "+f"(c[3])
        : "r"(a[0]), "r"(a[1]), "r"(a[2]), "r"(a[3]), "r"(b[0]), "r"(b[1]));
}

__global__ void __launch_bounds__(256, 1)
k_gemm(const float* __restrict__ x, const float* __restrict__ w,
       const float* __restrict__ bias, float* __restrict__ out) {
    extern __shared__ float sm[];
    const int row0 = blockIdx.x * BM;
    if (row0 >= g_offsets[NUM_E]) return;

    int e = 0;
#pragma unroll
    for (int i = 1; i < NUM_E; i++) e += (row0 >= g_offsets[i]);
    const int K     = 8 << e;       // expert's real K
    const int lds   = K + 4;        // padded smem stride (floats); lds%32 in {12,20,4} -> conflict-free
    const int kq    = K >> 2;       // float4 per row
    const int kq_sh = e + 1;        // log2(kq)

    float* sA = sm;                 // [BM][lds]
    float* sB = sm + BM * 132;      // [BN][lds]
    const int tx = threadIdx.x;

    // ---- load gathered A tile (x rows of this expert), only first K features ----
    for (int i = tx; i < BM * kq; i += 256) {
        int r = i >> kq_sh, c = i & (kq - 1);
        int tok = g_rows[row0 + r];
        tok = tok < 0 ? 0 : tok;    // padding rows: load token 0, result discarded
        float4 v = *((const float4*)(x + (size_t)tok * MAXF) + c);
        *(float4*)(sA + r * lds + (c << 2)) = v;
    }

    const int warp = tx >> 5, lane = tx & 31;
    const int wm = warp >> 2, wn = warp & 3;     // 2x4 warps -> 64x32 warp tiles
    const int grp = lane >> 2, qid = lane & 3;

    // loop over all 4 N-tiles reusing sA (x read once per token)
    for (int nt = 0; nt < OUTF / BN; nt++) {
        const int n0 = nt * BN;
        __syncthreads();   // A stores done (iter 0) / previous compute done reading sB

        const float* wb = w + ((size_t)e * OUTF + n0) * MAXF;
        for (int i = tx; i < BN * kq; i += 256) {
            int r = i >> kq_sh, c = i & (kq - 1);
            float4 v = *((const float4*)(wb + r * MAXF) + c);
            *(float4*)(sB + r * lds + (c << 2)) = v;
        }
        __syncthreads();

        float acc[4][4][4];
#pragma unroll
        for (int a0 = 0; a0 < 4; a0++)
#pragma unroll
            for (int b0 = 0; b0 < 4; b0++)
#pragma unroll
                for (int c0 = 0; c0 < 4; c0++) acc[a0][b0][c0] = 0.f;

        for (int ks = 0; ks < K; ks += 8) {
            uint32_t ah[4][4], al[4][4];
#pragma unroll
            for (int mf = 0; mf < 4; mf++) {
                const float* ap = sA + (wm * 64 + mf * 16 + grp) * lds + ks + qid;
                split_tf32(ap[0],           ah[mf][0], al[mf][0]);
                split_tf32(ap[8 * lds],     ah[mf][1], al[mf][1]);
                split_tf32(ap[4],           ah[mf][2], al[mf][2]);
                split_tf32(ap[8 * lds + 4], ah[mf][3], al[mf][3]);
            }
#pragma unroll
            for (int nf = 0; nf < 4; nf++) {
                const float* bp = sB + (wn * 32 + nf * 8 + grp) * lds + ks + qid;
                uint32_t bh[2], bl[2];
                split_tf32(bp[0], bh[0], bl[0]);
                split_tf32(bp[4], bh[1], bl[1]);
#pragma unroll
                for (int mf = 0; mf < 4; mf++) {
                    mma8(acc[mf][nf], ah[mf], bh);   // hi*hi
                    mma8(acc[mf][nf], al[mf], bh);   // lo*hi
                    mma8(acc[mf][nf], ah[mf], bl);   // hi*lo
                }
            }
        }

        // ---- scatter epilogue: out[token] = acc + bias[e] ----
#pragma unroll
        for (int mf = 0; mf < 4; mf++) {
            int r0 = row0 + wm * 64 + mf * 16 + grp;
            int t0 = g_rows[r0];
            int t1 = g_rows[r0 + 8];
#pragma unroll
            for (int nf = 0; nf < 4; nf++) {
                int c = n0 + wn * 32 + nf * 8 + (qid << 1);
                float2 bv = *(const float2*)(bias + e * OUTF + c);
                if (t0 >= 0) {
                    float2 o = make_float2(acc[mf][nf][0] + bv.x, acc[mf][nf][1] + bv.y);
                    *(float2*)(out + (size_t)t0 * OUTF + c) = o;
                }
                if (t1 >= 0) {
                    float2 o = make_float2(acc[mf][nf][2] + bv.x, acc[mf][nf][3] + bv.y);
                    *(float2*)(out + (size_t)t1 * OUTF + c) = o;
                }
            }
        }
    }
}

// ---------------- launch ----------------
extern "C" void kernel_launch(void* const* d_in, const int* in_sizes, int n_in,
                              void* d_out, int out_size) {
    (void)in_sizes; (void)n_in; (void)out_size;
    const float* x    = (const float*)d_in[0];
    const int*   feat = (const int*)d_in[1];     // int32 or int64, auto-detected on device
    const float* w    = (const float*)d_in[2];
    const float* b    = (const float*)d_in[3];
    float*       out  = (float*)d_out;

    cudaFuncSetAttribute(k_gemm, cudaFuncAttributeMaxDynamicSharedMemorySize, SMEM_BYTES);

    k_count  <<<(NTOK + 255) / 256, 256>>>(feat);
    k_offsets<<<1, 256>>>();
    k_scatter<<<(NTOK + 255) / 256, 256>>>(feat);
    k_gemm   <<<MAX_MTILES, 256, SMEM_BYTES>>>(x, w, b, out);
}

// round 7
// speedup vs baseline: 1.3817x; 1.3817x over previous
#include <cuda_runtime.h>
#include <cstdint>

#define NUM_E      5
#define NTOK       (16 * 2048)
#define OUTF       512
#define MAXF       128
#define BM         64
#define MAX_ROWS   (NTOK + NUM_E * BM)
#define MAX_MTILES (MAX_ROWS / BM)
// max smem across instantiations: K=128/BN=64 path: (64 + 2*64) * 132 * 4
#define SMEM_BYTES ((64 + 2 * 64) * 132 * 4)

// ---------------- scratch (static device globals; zero-initialized at load) ---------------
__device__ int g_counts[NUM_E];        // invariant: zero at entry of k_count (reset by k_offsets)
__device__ int g_offsets[NUM_E + 1];   // BM-aligned exclusive scan of counts
__device__ int g_slot[NTOK];           // slot of token within its expert bucket
__device__ int g_rows[MAX_ROWS];       // gathered row -> token id (-1 = padding)

// in_feat_size may be int32 or int64. Values in {8,16,32,64,128} (never 0), little-endian:
// if int64, word[1] (high half of elem 0) is 0.
__device__ __forceinline__ int expert_of(const int* __restrict__ feat, int t) {
    int is64 = (feat[1] == 0) ? 1 : 0;
    int v = feat[is64 ? (t << 1) : t];
    return __ffs(v) - 4;   // 8->0 ... 128->4
}

__global__ void k_count(const int* __restrict__ feat) {
    int t = blockIdx.x * blockDim.x + threadIdx.x;
    if (t >= NTOK) return;                      // NTOK % 256 == 0 -> full warps
    int e = expert_of(feat, t);
    unsigned m = __match_any_sync(0xffffffffu, e);
    int lane   = threadIdx.x & 31;
    int leader = __ffs(m) - 1;
    int rank   = __popc(m & ((1u << lane) - 1u));
    int base   = 0;
    if (lane == leader) base = atomicAdd(&g_counts[e], __popc(m));
    base = __shfl_sync(0xffffffffu, base, leader);
    g_slot[t] = base + rank;
}

__global__ void k_offsets() {
    if (threadIdx.x == 0) {
        int acc = 0;
        for (int e = 0; e < NUM_E; e++) {
            g_offsets[e] = acc;
            acc += (g_counts[e] + BM - 1) / BM * BM;
        }
        g_offsets[NUM_E] = acc;
    }
    __syncthreads();
    for (int e = 0; e < NUM_E; e++) {
        int s  = g_offsets[e] + g_counts[e];
        int en = g_offsets[e + 1];
        for (int i = s + (int)threadIdx.x; i < en; i += blockDim.x) g_rows[i] = -1;
    }
    __syncthreads();
    if (threadIdx.x < NUM_E) g_counts[threadIdx.x] = 0;   // reset for next graph replay
}

__global__ void k_scatter(const int* __restrict__ feat) {
    int t = blockIdx.x * blockDim.x + threadIdx.x;
    if (t >= NTOK) return;
    int e = expert_of(feat, t);
    g_rows[g_offsets[e] + g_slot[t]] = t;
}

// ---------------- 3xTF32 helpers ----------------
__device__ __forceinline__ void split_tf32(float f, uint32_t& hi, uint32_t& lo) {
    asm("cvt.rna.tf32.f32 %0, %1;" : "=r"(hi) : "f"(f));
    float lf = f - __uint_as_float(hi);
    asm("cvt.rna.tf32.f32 %0, %1;" : "=r"(lo) : "f"(lf));
}

__device__ __forceinline__ void mma8(float* c, const uint32_t* a, const uint32_t* b) {
    asm volatile(
        "mma.sync.aligned.m16n8k8.row.col.f32.tf32.tf32.f32 "
        "{%0,%1,%2,%3}, {%4,%5,%6,%7}, {%8,%9}, {%0,%1,%2,%3};\n"
        : "+f"(c[0]), "+f"(c[1]), "+f"(c[2]), "+f"(c[3])
        : "r"(a[0]), "r"(a[1]), "r"(a[2]), "r"(a[3]), "r"(b[0]), "r"(b[1]));
}

__device__ __forceinline__ void cpa16(void* sptr, const void* gptr) {
    uint32_t s = (uint32_t)__cvta_generic_to_shared(sptr);
    asm volatile("cp.async.cg.shared.global [%0], [%1], 16;\n" :: "r"(s), "l"(gptr) : "memory");
}
#define CP_COMMIT() asm volatile("cp.async.commit_group;\n" ::: "memory")
#define CP_WAIT1()  asm volatile("cp.async.wait_group 1;\n" ::: "memory")

// ---------------- templated expert GEMM (BM=64 rows x OUTF cols, N-looped) ----------------
template <int K, int BN>
__device__ __forceinline__ void gemm_expert(
    int row0,
    const float* __restrict__ x,
    const float* __restrict__ we,    // w + e*OUTF*MAXF
    const float* __restrict__ be,    // bias + e*OUTF
    float* __restrict__ out,
    float* sm)
{
    constexpr int lds = K + 4;            // lds%32 in {12,20,4,...} -> conflict-free frag loads
    constexpr int kq  = K >> 2;           // float4 per row
    constexpr int NT  = OUTF / BN;
    constexpr int NF  = BN / 32;          // 8-col fragments per warp (warp covers BN/4 cols)

    float* sA  = sm;                      // [BM][lds]
    float* sB0 = sm + BM * lds;           // [BN][lds] x2 buffers
    float* sB1 = sB0 + BN * lds;

    const int tx = threadIdx.x;

    // ---- A tile (gathered x rows), group 0 together with B(0) ----
    #pragma unroll
    for (int i = tx; i < BM * kq; i += 256) {
        int r = i / kq, c = i % kq;
        int tok = g_rows[row0 + r];
        tok = tok < 0 ? 0 : tok;                      // padding row: dummy load, discarded
        cpa16(sA + r * lds + (c << 2), x + (size_t)tok * MAXF + (c << 2));
    }
    #pragma unroll
    for (int i = tx; i < BN * kq; i += 256) {
        int r = i / kq, c = i % kq;
        cpa16(sB0 + r * lds + (c << 2), we + (size_t)r * MAXF + (c << 2));
    }
    CP_COMMIT();                                      // group: A + B(0)
    if (NT > 1) {
        #pragma unroll
        for (int i = tx; i < BN * kq; i += 256) {
            int r = i / kq, c = i % kq;
            cpa16(sB1 + r * lds + (c << 2), we + (size_t)(BN + r) * MAXF + (c << 2));
        }
    }
    CP_COMMIT();                                      // group: B(1) (possibly empty)

    const int warp = tx >> 5, lane = tx & 31;
    const int wm = warp >> 2, wn = warp & 3;          // 2x4 warps -> 32 x (BN/4) warp tiles
    const int grp = lane >> 2, qid = lane & 3;

    for (int nt = 0; nt < NT; nt++) {
        CP_WAIT1();                                   // B(nt) (and A) landed
        __syncthreads();
        float* sB = (nt & 1) ? sB1 : sB0;

        float acc[2][NF][4];
        #pragma unroll
        for (int mf = 0; mf < 2; mf++)
            #pragma unroll
            for (int nf = 0; nf < NF; nf++)
                #pragma unroll
                for (int q = 0; q < 4; q++) acc[mf][nf][q] = 0.f;

        #pragma unroll
        for (int ks = 0; ks < K; ks += 8) {
            uint32_t ah[2][4], al[2][4];
            #pragma unroll
            for (int mf = 0; mf < 2; mf++) {
                const float* ap = sA + (wm * 32 + mf * 16 + grp) * lds + ks + qid;
                split_tf32(ap[0],           ah[mf][0], al[mf][0]);
                split_tf32(ap[8 * lds],     ah[mf][1], al[mf][1]);
                split_tf32(ap[4],           ah[mf][2], al[mf][2]);
                split_tf32(ap[8 * lds + 4], ah[mf][3], al[mf][3]);
            }
            #pragma unroll
            for (int nf = 0; nf < NF; nf++) {
                const float* bp = sB + (wn * (BN / 4) + nf * 8 + grp) * lds + ks + qid;
                uint32_t bh[2], bl[2];
                split_tf32(bp[0], bh[0], bl[0]);
                split_tf32(bp[4], bh[1], bl[1]);
                #pragma unroll
                for (int mf = 0; mf < 2; mf++) {
                    mma8(acc[mf][nf], ah[mf], bh);    // hi*hi
                    mma8(acc[mf][nf], al[mf], bh);    // lo*hi
                    mma8(acc[mf][nf], ah[mf], bl);    // hi*lo
                }
            }
        }

        // ---- scatter epilogue ----
        const int n0 = nt * BN;
        #pragma unroll
        for (int mf = 0; mf < 2; mf++) {
            int r  = row0 + wm * 32 + mf * 16 + grp;
            int t0 = g_rows[r];
            int t1 = g_rows[r + 8];
            #pragma unroll
            for (int nf = 0; nf < NF; nf++) {
                int c = n0 + wn * (BN / 4) + nf * 8 + (qid << 1);
                float2 bv = *(const float2*)(be + c);
                if (t0 >= 0) {
                    float2 o = make_float2(acc[mf][nf][0] + bv.x, acc[mf][nf][1] + bv.y);
                    *(float2*)(out + (size_t)t0 * OUTF + c) = o;
                }
                if (t1 >= 0) {
                    float2 o = make_float2(acc[mf][nf][2] + bv.x, acc[mf][nf][3] + bv.y);
                    *(float2*)(out + (size_t)t1 * OUTF + c) = o;
                }
            }
        }

        __syncthreads();                              // all warps done reading sB buffer
        if (nt + 2 < NT) {
            float* sBn = (nt & 1) ? sB1 : sB0;        // reuse the buffer just drained
            #pragma unroll
            for (int i = tx; i < BN * kq; i += 256) {
                int r = i / kq, c = i % kq;
                cpa16(sBn + r * lds + (c << 2), we + (size_t)((nt + 2) * BN + r) * MAXF + (c << 2));
            }
        }
        CP_COMMIT();                                  // always commit (maybe empty) -> wait1 invariant
    }
}

__global__ void __launch_bounds__(256, 2)
k_gemm(const float* __restrict__ x, const float* __restrict__ w,
       const float* __restrict__ bias, float* __restrict__ out) {
    extern __shared__ float sm[];
    const int row0 = blockIdx.x * BM;
    if (row0 >= g_offsets[NUM_E]) return;

    int e = 0;
    #pragma unroll
    for (int i = 1; i < NUM_E; i++) e += (row0 >= g_offsets[i]);

    const float* we = w + (size_t)e * OUTF * MAXF;
    const float* be = bias + e * OUTF;

    switch (e) {
        case 0: gemm_expert<  8, 128>(row0, x, we, be, out, sm); break;
        case 1: gemm_expert< 16, 128>(row0, x, we, be, out, sm); break;
        case 2: gemm_expert< 32, 128>(row0, x, we, be, out, sm); break;
        case 3: gemm_expert< 64, 128>(row0, x, we, be, out, sm); break;
        default: gemm_expert<128, 64>(row0, x, we, be, out, sm); break;
    }
}

// ---------------- launch ----------------
extern "C" void kernel_launch(void* const* d_in, const int* in_sizes, int n_in,
                              void* d_out, int out_size) {
    (void)in_sizes; (void)n_in; (void)out_size;
    const float* x    = (const float*)d_in[0];
    const int*   feat = (const int*)d_in[1];
    const float* w    = (const float*)d_in[2];
    const float* b    = (const float*)d_in[3];
    float*       out  = (float*)d_out;

    cudaFuncSetAttribute(k_gemm, cudaFuncAttributeMaxDynamicSharedMemorySize, SMEM_BYTES);

    k_count  <<<(NTOK + 255) / 256, 256>>>(feat);
    k_offsets<<<1, 256>>>();
    k_scatter<<<(NTOK + 255) / 256, 256>>>(feat);
    k_gemm   <<<MAX_MTILES, 256, SMEM_BYTES>>>(x, w, b, out);
}

// round 8
// speedup vs baseline: 1.5347x; 1.1107x over previous
#include <cuda_runtime.h>
#include <cstdint>

#define NUM_E      5
#define NTOK       (16 * 2048)
#define OUTF       512
#define MAXF       128
#define BM         32
#define MAX_ROWS   (NTOK + NUM_E * BM)
#define MAX_MTILES (MAX_ROWS / BM)
// worst smem: K=128 path: A frag 32KB + 2*64*132*4 B + tokens
#define SMEM_BYTES (8192 * 4 + 2 * 64 * 132 * 4 + 256)

// ---------------- scratch (static device globals; zero-initialized at load) ---------------
__device__ int g_counts[NUM_E];
__device__ int g_offsets[NUM_E + 1];   // BM-aligned exclusive scan
__device__ int g_slot[NTOK];
__device__ int g_rows[MAX_ROWS];       // gathered row -> token id (-1 = padding)

// in_feat_size may be int32 or int64. Values in {8,16,32,64,128}; if int64, word[1]==0.
__device__ __forceinline__ int expert_of(const int* __restrict__ feat, int t) {
    int is64 = (feat[1] == 0) ? 1 : 0;
    int v = feat[is64 ? (t << 1) : t];
    return __ffs(v) - 4;   // 8->0 ... 128->4
}

__global__ void k_count(const int* __restrict__ feat) {
    int t = blockIdx.x * blockDim.x + threadIdx.x;
    if (t >= NTOK) return;
    int e = expert_of(feat, t);
    unsigned m = __match_any_sync(0xffffffffu, e);
    int lane   = threadIdx.x & 31;
    int leader = __ffs(m) - 1;
    int rank   = __popc(m & ((1u << lane) - 1u));
    int base   = 0;
    if (lane == leader) base = atomicAdd(&g_counts[e], __popc(m));
    base = __shfl_sync(0xffffffffu, base, leader);
    g_slot[t] = base + rank;
}

__global__ void k_offsets() {
    if (threadIdx.x == 0) {
        int acc = 0;
        for (int e = 0; e < NUM_E; e++) {
            g_offsets[e] = acc;
            acc += (g_counts[e] + BM - 1) / BM * BM;
        }
        g_offsets[NUM_E] = acc;
    }
    __syncthreads();
    for (int e = 0; e < NUM_E; e++) {
        int s  = g_offsets[e] + g_counts[e];
        int en = g_offsets[e + 1];
        for (int i = s + (int)threadIdx.x; i < en; i += blockDim.x) g_rows[i] = -1;
    }
    __syncthreads();
    if (threadIdx.x < NUM_E) g_counts[threadIdx.x] = 0;   // reset for next graph replay
}

__global__ void k_scatter(const int* __restrict__ feat) {
    int t = blockIdx.x * blockDim.x + threadIdx.x;
    if (t >= NTOK) return;
    int e = expert_of(feat, t);
    g_rows[g_offsets[e] + g_slot[t]] = t;
}

// ---------------- 3xTF32 helpers ----------------
__device__ __forceinline__ void split_tf32(float f, uint32_t& hi, uint32_t& lo) {
    asm("cvt.rna.tf32.f32 %0, %1;" : "=r"(hi) : "f"(f));
    float lf = f - __uint_as_float(hi);
    asm("cvt.rna.tf32.f32 %0, %1;" : "=r"(lo) : "f"(lf));
}

__device__ __forceinline__ void mma8(float* c, const uint32_t* a, const uint32_t* b) {
    asm volatile(
        "mma.sync.aligned.m16n8k8.row.col.f32.tf32.tf32.f32 "
        "{%0,%1,%2,%3}, {%4,%5,%6,%7}, {%8,%9}, {%0,%1,%2,%3};\n"
        : "+f"(c[0]), "+f"(c[1]), "+f"(c[2]), "+f"(c[3])
        : "r"(a[0]), "r"(a[1]), "r"(a[2]), "r"(a[3]), "r"(b[0]), "r"(b[1]));
}

__device__ __forceinline__ void cpa16(void* sptr, const void* gptr) {
    uint32_t s = (uint32_t)__cvta_generic_to_shared(sptr);
    asm volatile("cp.async.cg.shared.global [%0], [%1], 16;\n" :: "r"(s), "l"(gptr) : "memory");
}
#define CP_COMMIT() asm volatile("cp.async.commit_group;\n" ::: "memory")
#define CP_WAIT1()  asm volatile("cp.async.wait_group 1;\n" ::: "memory")

// ---------------- templated expert GEMM: BM=32 rows, N looped in BN tiles --------------
// Warp layout: 8 warps side-by-side over N (each warp owns distinct BN/8 cols);
// each warp covers both 16-row m-tiles. A is pre-split to tf32 hi/lo in
// m16n8k8 fragment order (split once), B raw in smem, split inline (once/elem).
template <int K, int BN>
__device__ __forceinline__ void gemm_expert(
    int row0,
    const float* __restrict__ x,
    const float* __restrict__ we,    // w + e*OUTF*MAXF
    const float* __restrict__ be,    // bias + e*OUTF
    float* __restrict__ out,
    uint32_t* sm)
{
    constexpr int LOGK = (K == 8) ? 3 : (K == 16) ? 4 : (K == 32) ? 5 : (K == 64) ? 6 : 7;
    constexpr int lds  = K + 4;          // padded stride: conflict-free B frag reads
    constexpr int kq   = K >> 2;         // float4 per row
    constexpr int NT   = OUTF / BN;
    constexpr int NF   = BN / 64;        // n8 tiles per warp
    constexpr int KS   = K / 8;

    uint32_t* sAh = sm;                              // [KS*2*32*4] frag-ordered hi
    uint32_t* sAl = sAh + KS * 256;                  // frag-ordered lo
    float*    sB0 = (float*)(sAl + KS * 256);        // [BN][lds] raw, double-buffered
    float*    sB1 = sB0 + BN * lds;
    int*      s_tok = (int*)(sB1 + BN * lds);        // 32 gathered token ids

    const int tx = threadIdx.x;

    // ---- B(0) in flight first (needed earliest) ----
    #pragma unroll
    for (int i = tx; i < BN * kq; i += 256) {
        int r = i / kq, c = i % kq;
        cpa16(sB0 + r * lds + (c << 2), we + (size_t)r * MAXF + (c << 2));
    }
    CP_COMMIT();                                     // group 0: B(0)

    // ---- gathered tokens ----
    if (tx < 32) {
        int t = g_rows[row0 + tx];
        s_tok[tx] = t < 0 ? 0 : t;                   // padding: dummy token, discarded later
    }
    __syncthreads();

    // ---- A pre-split: LDG -> split -> STS in m16n8k8 fragment order ----
    #pragma unroll 4
    for (int i = tx; i < 32 * K; i += 256) {
        int r = i >> LOGK, k = i & (K - 1);
        float v = x[(size_t)s_tok[r] * MAXF + k];
        uint32_t hi, lo; split_tf32(v, hi, lo);
        int rw = r & 15, mt = r >> 4;
        int ks = k >> 3, h = (k >> 2) & 1, q = k & 3;
        int dl  = ((rw & 7) << 2) | q;                       // dest lane
        int j   = ((rw >> 3) & 1) | (h << 1);                // frag reg index
        int idx = ((ks * 2 + mt) * 32 + dl) * 4 + j;
        sAh[idx] = hi; sAl[idx] = lo;
    }

    // ---- B(1) in flight ----
    if (NT > 1) {
        #pragma unroll
        for (int i = tx; i < BN * kq; i += 256) {
            int r = i / kq, c = i % kq;
            cpa16(sB1 + r * lds + (c << 2), we + (size_t)(BN + r) * MAXF + (c << 2));
        }
    }
    CP_COMMIT();                                     // group 1: B(1) (maybe empty)

    const int warp = tx >> 5, lane = tx & 31;
    const int grp = lane >> 2, qid = lane & 3;

    for (int nt = 0; nt < NT; nt++) {
        CP_WAIT1();                                  // B(nt) landed
        __syncthreads();                             // + A frag STS visible (nt==0)
        const float* sB = (nt & 1) ? sB1 : sB0;

        float acc[2][NF][4];
        #pragma unroll
        for (int mt = 0; mt < 2; mt++)
            #pragma unroll
            for (int nf = 0; nf < NF; nf++)
                #pragma unroll
                for (int q = 0; q < 4; q++) acc[mt][nf][q] = 0.f;

        #pragma unroll
        for (int ks = 0; ks < KS; ks++) {
            uint32_t ah[2][4], al[2][4];
            #pragma unroll
            for (int mt = 0; mt < 2; mt++) {
                uint4 vh = *(const uint4*)(sAh + ((ks * 2 + mt) * 32 + lane) * 4);
                uint4 vl = *(const uint4*)(sAl + ((ks * 2 + mt) * 32 + lane) * 4);
                ah[mt][0] = vh.x; ah[mt][1] = vh.y; ah[mt][2] = vh.z; ah[mt][3] = vh.w;
                al[mt][0] = vl.x; al[mt][1] = vl.y; al[mt][2] = vl.z; al[mt][3] = vl.w;
            }
            #pragma unroll
            for (int nf = 0; nf < NF; nf++) {
                const float* bp = sB + (warp * (BN / 8) + nf * 8 + grp) * lds + ks * 8 + qid;
                uint32_t bh[2], bl[2];
                split_tf32(bp[0], bh[0], bl[0]);
                split_tf32(bp[4], bh[1], bl[1]);
                #pragma unroll
                for (int mt = 0; mt < 2; mt++) {
                    mma8(acc[mt][nf], ah[mt], bh);   // hi*hi
                    mma8(acc[mt][nf], al[mt], bh);   // lo*hi
                    mma8(acc[mt][nf], ah[mt], bl);   // hi*lo
                }
            }
        }

        // ---- scatter epilogue ----
        const int n0 = nt * BN;
        #pragma unroll
        for (int mt = 0; mt < 2; mt++) {
            int r  = row0 + mt * 16 + grp;
            int t0 = g_rows[r];
            int t1 = g_rows[r + 8];
            #pragma unroll
            for (int nf = 0; nf < NF; nf++) {
                int c = n0 + warp * (BN / 8) + nf * 8 + (qid << 1);
                float2 bv = *(const float2*)(be + c);
                if (t0 >= 0) {
                    float2 o = make_float2(acc[mt][nf][0] + bv.x, acc[mt][nf][1] + bv.y);
                    *(float2*)(out + (size_t)t0 * OUTF + c) = o;
                }
                if (t1 >= 0) {
                    float2 o = make_float2(acc[mt][nf][2] + bv.x, acc[mt][nf][3] + bv.y);
                    *(float2*)(out + (size_t)t1 * OUTF + c) = o;
                }
            }
        }

        __syncthreads();                             // sB buffer drained by all warps
        if (nt + 2 < NT) {
            float* sBn = (nt & 1) ? sB1 : sB0;
            #pragma unroll
            for (int i = tx; i < BN * kq; i += 256) {
                int r = i / kq, c = i % kq;
                cpa16(sBn + r * lds + (c << 2), we + (size_t)((nt + 2) * BN + r) * MAXF + (c << 2));
            }
        }
        CP_COMMIT();                                 // keep wait_group(1) invariant
    }
}

__global__ void __launch_bounds__(256, 2)
k_gemm(const float* __restrict__ x, const float* __restrict__ w,
       const float* __restrict__ bias, float* __restrict__ out) {
    extern __shared__ uint32_t sm[];
    // reversed order: heavy K=128 blocks (highest rows) scheduled FIRST
    const int total = g_offsets[NUM_E];
    const int row0  = total - (int)(blockIdx.x + 1) * BM;
    if (row0 < 0) return;

    int e = 0;
    #pragma unroll
    for (int i = 1; i < NUM_E; i++) e += (row0 >= g_offsets[i]);

    const float* we = w + (size_t)e * OUTF * MAXF;
    const float* be = bias + e * OUTF;

    switch (e) {
        case 0:  gemm_expert<  8, 256>(row0, x, we, be, out, sm); break;
        case 1:  gemm_expert< 16, 256>(row0, x, we, be, out, sm); break;
        case 2:  gemm_expert< 32, 256>(row0, x, we, be, out, sm); break;
        case 3:  gemm_expert< 64, 128>(row0, x, we, be, out, sm); break;
        default: gemm_expert<128,  64>(row0, x, we, be, out, sm); break;
    }
}

// ---------------- launch ----------------
extern "C" void kernel_launch(void* const* d_in, const int* in_sizes, int n_in,
                              void* d_out, int out_size) {
    (void)in_sizes; (void)n_in; (void)out_size;
    const float* x    = (const float*)d_in[0];
    const int*   feat = (const int*)d_in[1];
    const float* w    = (const float*)d_in[2];
    const float* b    = (const float*)d_in[3];
    float*       out  = (float*)d_out;

    cudaFuncSetAttribute(k_gemm, cudaFuncAttributeMaxDynamicSharedMemorySize, SMEM_BYTES);

    k_count  <<<(NTOK + 255) / 256, 256>>>(feat);
    k_offsets<<<1, 256>>>();
    k_scatter<<<(NTOK + 255) / 256, 256>>>(feat);
    k_gemm   <<<MAX_MTILES, 256, SMEM_BYTES>>>(x, w, b, out);
}

// round 9
// speedup vs baseline: 1.5847x; 1.0326x over previous
#include <cuda_runtime.h>
#include <cstdint>

#define NUM_E      5
#define NTOK       (16 * 2048)
#define OUTF       512
#define MAXF       128
#define BM         64
#define MAX_ROWS   (NTOK + NUM_E * BM)
#define MAX_MTILES (MAX_ROWS / BM)
// worst smem: K=128: A 64*132*4 + B 2*64*132*4
#define SMEM_BYTES ((64 * 132 + 2 * 64 * 132) * 4)

// ---------------- scratch (static device globals; zero-initialized at load) ---------------
__device__ int g_counts[NUM_E];
__device__ int g_offsets[NUM_E + 1];   // BM-aligned exclusive scan
__device__ int g_slot[NTOK];
__device__ int g_rows[MAX_ROWS];       // gathered row -> token id (-1 = padding)

// in_feat_size may be int32 or int64. Values in {8,16,32,64,128}; if int64, word[1]==0.
__device__ __forceinline__ int expert_of(const int* __restrict__ feat, int t) {
    int is64 = (feat[1] == 0) ? 1 : 0;
    int v = feat[is64 ? (t << 1) : t];
    return __ffs(v) - 4;   // 8->0 ... 128->4
}

__global__ void k_count(const int* __restrict__ feat) {
    int t = blockIdx.x * blockDim.x + threadIdx.x;
    if (t >= NTOK) return;
    int e = expert_of(feat, t);
    unsigned m = __match_any_sync(0xffffffffu, e);
    int lane   = threadIdx.x & 31;
    int leader = __ffs(m) - 1;
    int rank   = __popc(m & ((1u << lane) - 1u));
    int base   = 0;
    if (lane == leader) base = atomicAdd(&g_counts[e], __popc(m));
    base = __shfl_sync(0xffffffffu, base, leader);
    g_slot[t] = base + rank;
}

__global__ void k_offsets() {
    if (threadIdx.x == 0) {
        int acc = 0;
        for (int e = 0; e < NUM_E; e++) {
            g_offsets[e] = acc;
            acc += (g_counts[e] + BM - 1) / BM * BM;
        }
        g_offsets[NUM_E] = acc;
    }
    __syncthreads();
    for (int e = 0; e < NUM_E; e++) {
        int s  = g_offsets[e] + g_counts[e];
        int en = g_offsets[e + 1];
        for (int i = s + (int)threadIdx.x; i < en; i += blockDim.x) g_rows[i] = -1;
    }
    __syncthreads();
    if (threadIdx.x < NUM_E) g_counts[threadIdx.x] = 0;   // reset for next graph replay
}

__global__ void k_scatter(const int* __restrict__ feat) {
    int t = blockIdx.x * blockDim.x + threadIdx.x;
    if (t >= NTOK) return;
    int e = expert_of(feat, t);
    g_rows[g_offsets[e] + g_slot[t]] = t;
}

// ---------------- 3xTF32 helpers ----------------
__device__ __forceinline__ void split_tf32(float f, uint32_t& hi, uint32_t& lo) {
    asm("cvt.rna.tf32.f32 %0, %1;" : "=r"(hi) : "f"(f));
    float lf = f - __uint_as_float(hi);
    asm("cvt.rna.tf32.f32 %0, %1;" : "=r"(lo) : "f"(lf));
}

__device__ __forceinline__ void mma8(float* c, const uint32_t* a, const uint32_t* b) {
    asm volatile(
        "mma.sync.aligned.m16n8k8.row.col.f32.tf32.tf32.f32 "
        "{%0,%1,%2,%3}, {%4,%5,%6,%7}, {%8,%9}, {%0,%1,%2,%3};\n"
        : "+f"(c[0]), "+f"(c[1]), "+f"(c[2]), "+f"(c[3])
        : "r"(a[0]), "r"(a[1]), "r"(a[2]), "r"(a[3]), "r"(b[0]), "r"(b[1]));
}

__device__ __forceinline__ void cpa16(void* sptr, const void* gptr) {
    uint32_t s = (uint32_t)__cvta_generic_to_shared(sptr);
    asm volatile("cp.async.cg.shared.global [%0], [%1], 16;\n" :: "r"(s), "l"(gptr) : "memory");
}
#define CP_COMMIT() asm volatile("cp.async.commit_group;\n" ::: "memory")
#define CP_WAIT1()  asm volatile("cp.async.wait_group 1;\n" ::: "memory")

// ---------------- templated expert GEMM --------------------------------------------------
// BM=64 rows x OUTF cols. 8 warps = 4 over M x 2 over N. Each warp: one m16 tile,
// NF=4 n8 tiles (32 cols) per N-pass; NT=8 passes of BN=64 with double-buffered B.
// A raw row-major in smem (cp.async-gathered), split to tf32 hi/lo in-register.
// AREG: for small K, A fragments hoisted into registers once per block.
template <int K, bool AREG>
__device__ __forceinline__ void gemm_expert(
    int row0,
    const float* __restrict__ x,
    const float* __restrict__ we,    // w + e*OUTF*MAXF
    const float* __restrict__ be,    // bias + e*OUTF
    float* __restrict__ out,
    float* sm)
{
    constexpr int BN  = 64;
    constexpr int NT  = OUTF / BN;       // 8
    constexpr int NF  = 4;               // n8 tiles per warp
    constexpr int KS  = K / 8;
    constexpr int lds = K + 4;           // padded stride -> conflict-free scalar frag reads
    constexpr int kq  = K >> 2;          // float4 per row
    constexpr int KSR = AREG ? KS : 1;

    float* sA  = sm;                     // [BM][lds]
    float* sB0 = sm + BM * lds;          // [BN][lds] double-buffered
    float* sB1 = sB0 + BN * lds;

    const int tx = threadIdx.x;

    // ---- group 0: gathered A + B(0) ----
    #pragma unroll
    for (int i = tx; i < BM * kq; i += 256) {
        int r = i / kq, c = i % kq;
        int tok = g_rows[row0 + r];
        tok = tok < 0 ? 0 : tok;                       // padding row: dummy, discarded later
        cpa16(sA + r * lds + (c << 2), x + (size_t)tok * MAXF + (c << 2));
    }
    #pragma unroll
    for (int i = tx; i < BN * kq; i += 256) {
        int r = i / kq, c = i % kq;
        cpa16(sB0 + r * lds + (c << 2), we + (size_t)r * MAXF + (c << 2));
    }
    CP_COMMIT();
    // ---- group 1: B(1) ----
    #pragma unroll
    for (int i = tx; i < BN * kq; i += 256) {
        int r = i / kq, c = i % kq;
        cpa16(sB1 + r * lds + (c << 2), we + (size_t)(BN + r) * MAXF + (c << 2));
    }
    CP_COMMIT();

    const int warp = tx >> 5, lane = tx & 31;
    const int wm = warp & 3, wn = warp >> 2;           // 4 M-warps x 2 N-warps
    const int grp = lane >> 2, qid = lane & 3;

    const int t0 = g_rows[row0 + wm * 16 + grp];       // hoisted epilogue tokens
    const int t1 = g_rows[row0 + wm * 16 + grp + 8];
    const float* aBase = sA + (wm * 16 + grp) * lds + qid;

    uint32_t rah[KSR][4], ral[KSR][4];                 // A frags in regs (AREG path)

    for (int nt = 0; nt < NT; nt++) {
        CP_WAIT1();                                    // B(nt) (and A at nt=0) landed
        __syncthreads();
        const float* sB = (nt & 1) ? sB1 : sB0;

        if (AREG && nt == 0) {
            #pragma unroll
            for (int ks = 0; ks < KS; ks++) {
                const float* ap = aBase + ks * 8;
                split_tf32(ap[0],           rah[ks][0], ral[ks][0]);
                split_tf32(ap[8 * lds],     rah[ks][1], ral[ks][1]);
                split_tf32(ap[4],           rah[ks][2], ral[ks][2]);
                split_tf32(ap[8 * lds + 4], rah[ks][3], ral[ks][3]);
            }
        }

        float acc[NF][4] = {};

        #pragma unroll
        for (int ks = 0; ks < KS; ks++) {
            uint32_t ah[4], al[4];
            const uint32_t *pah, *pal;
            if (AREG) {
                pah = rah[ks]; pal = ral[ks];
            } else {
                const float* ap = aBase + ks * 8;
                split_tf32(ap[0],           ah[0], al[0]);
                split_tf32(ap[8 * lds],     ah[1], al[1]);
                split_tf32(ap[4],           ah[2], al[2]);
                split_tf32(ap[8 * lds + 4], ah[3], al[3]);
                pah = ah; pal = al;
            }
            #pragma unroll
            for (int nf = 0; nf < NF; nf++) {
                const float* bp = sB + (wn * 32 + nf * 8 + grp) * lds + ks * 8 + qid;
                uint32_t bh[2], bl[2];
                split_tf32(bp[0], bh[0], bl[0]);
                split_tf32(bp[4], bh[1], bl[1]);
                mma8(acc[nf], pah, bh);    // hi*hi
                mma8(acc[nf], pal, bh);    // lo*hi
                mma8(acc[nf], pah, bl);    // hi*lo
            }
        }

        // ---- scatter epilogue ----
        const int n0 = nt * BN + wn * 32;
        #pragma unroll
        for (int nf = 0; nf < NF; nf++) {
            int c = n0 + nf * 8 + (qid << 1);
            float2 bv = *(const float2*)(be + c);
            if (t0 >= 0) {
                float2 o = make_float2(acc[nf][0] + bv.x, acc[nf][1] + bv.y);
                *(float2*)(out + (size_t)t0 * OUTF + c) = o;
            }
            if (t1 >= 0) {
                float2 o = make_float2(acc[nf][2] + bv.x, acc[nf][3] + bv.y);
                *(float2*)(out + (size_t)t1 * OUTF + c) = o;
            }
        }

        __syncthreads();                               // buffer fully drained by all warps
        if (nt + 2 < NT) {
            float* sBn = (nt & 1) ? sB1 : sB0;
            #pragma unroll
            for (int i = tx; i < BN * kq; i += 256) {
                int r = i / kq, c = i % kq;
                cpa16(sBn + r * lds + (c << 2), we + (size_t)((nt + 2) * BN + r) * MAXF + (c << 2));
            }
        }
        CP_COMMIT();                                   // keep wait_group(1) invariant
    }
}

__global__ void __launch_bounds__(256, 2)
k_gemm(const float* __restrict__ x, const float* __restrict__ w,
       const float* __restrict__ bias, float* __restrict__ out) {
    extern __shared__ float sm[];
    // reversed order: heavy K=128 blocks (highest rows) scheduled FIRST
    const int total = g_offsets[NUM_E];
    const int row0  = total - (int)(blockIdx.x + 1) * BM;
    if (row0 < 0) return;

    int e = 0;
    #pragma unroll
    for (int i = 1; i < NUM_E; i++) e += (row0 >= g_offsets[i]);

    const float* we = w + (size_t)e * OUTF * MAXF;
    const float* be = bias + e * OUTF;

    switch (e) {
        case 0:  gemm_expert<  8, true >(row0, x, we, be, out, sm); break;
        case 1:  gemm_expert< 16, true >(row0, x, we, be, out, sm); break;
        case 2:  gemm_expert< 32, true >(row0, x, we, be, out, sm); break;
        case 3:  gemm_expert< 64, false>(row0, x, we, be, out, sm); break;
        default: gemm_expert<128, false>(row0, x, we, be, out, sm); break;
    }
}

// ---------------- launch ----------------
extern "C" void kernel_launch(void* const* d_in, const int* in_sizes, int n_in,
                              void* d_out, int out_size) {
    (void)in_sizes; (void)n_in; (void)out_size;
    const float* x    = (const float*)d_in[0];
    const int*   feat = (const int*)d_in[1];
    const float* w    = (const float*)d_in[2];
    const float* b    = (const float*)d_in[3];
    float*       out  = (float*)d_out;

    cudaFuncSetAttribute(k_gemm, cudaFuncAttributeMaxDynamicSharedMemorySize, SMEM_BYTES);

    k_count  <<<(NTOK + 255) / 256, 256>>>(feat);
    k_offsets<<<1, 256>>>();
    k_scatter<<<(NTOK + 255) / 256, 256>>>(feat);
    k_gemm   <<<MAX_MTILES, 256, SMEM_BYTES>>>(x, w, b, out);
}

// round 10
// speedup vs baseline: 1.6047x; 1.0126x over previous
#include <cuda_runtime.h>
#include <cstdint>

#define NUM_E      5
#define NTOK       (16 * 2048)
#define OUTF       512
#define MAXF       128
#define BM         64
#define MAX_ROWS   (NTOK + NUM_E * BM)
#define MAX_MTILES (MAX_ROWS / BM)
// worst smem: K=128: A 64*132*4 + B 2*64*132*4
#define SMEM_BYTES ((64 * 132 + 2 * 64 * 132) * 4)

// ---------------- scratch (static device globals; zero-initialized at load) ---------------
__device__ int g_counts[NUM_E];
__device__ int g_offsets[NUM_E + 1];   // BM-aligned exclusive scan
__device__ int g_slot[NTOK];
__device__ int g_rows[MAX_ROWS];       // gathered row -> token id (-1 = padding)

// in_feat_size may be int32 or int64. Values in {8,16,32,64,128}; if int64, word[1]==0.
__device__ __forceinline__ int expert_of(const int* __restrict__ feat, int t) {
    int is64 = (feat[1] == 0) ? 1 : 0;
    int v = feat[is64 ? (t << 1) : t];
    return __ffs(v) - 4;   // 8->0 ... 128->4
}

__global__ void k_count(const int* __restrict__ feat) {
    int t = blockIdx.x * blockDim.x + threadIdx.x;
    if (t >= NTOK) return;
    int e = expert_of(feat, t);
    unsigned m = __match_any_sync(0xffffffffu, e);
    int lane   = threadIdx.x & 31;
    int leader = __ffs(m) - 1;
    int rank   = __popc(m & ((1u << lane) - 1u));
    int base   = 0;
    if (lane == leader) base = atomicAdd(&g_counts[e], __popc(m));
    base = __shfl_sync(0xffffffffu, base, leader);
    g_slot[t] = base + rank;
}

__global__ void k_offsets() {
    if (threadIdx.x == 0) {
        int acc = 0;
        for (int e = 0; e < NUM_E; e++) {
            g_offsets[e] = acc;
            acc += (g_counts[e] + BM - 1) / BM * BM;
        }
        g_offsets[NUM_E] = acc;
    }
    __syncthreads();
    for (int e = 0; e < NUM_E; e++) {
        int s  = g_offsets[e] + g_counts[e];
        int en = g_offsets[e + 1];
        for (int i = s + (int)threadIdx.x; i < en; i += blockDim.x) g_rows[i] = -1;
    }
    __syncthreads();
    if (threadIdx.x < NUM_E) g_counts[threadIdx.x] = 0;   // reset for next graph replay
}

__global__ void k_scatter(const int* __restrict__ feat) {
    int t = blockIdx.x * blockDim.x + threadIdx.x;
    if (t >= NTOK) return;
    int e = expert_of(feat, t);
    g_rows[g_offsets[e] + g_slot[t]] = t;
}

// ---------------- 3xTF32 helpers ----------------
__device__ __forceinline__ void split_tf32(float f, uint32_t& hi, uint32_t& lo) {
    asm("cvt.rna.tf32.f32 %0, %1;" : "=r"(hi) : "f"(f));
    float lf = f - __uint_as_float(hi);
    asm("cvt.rna.tf32.f32 %0, %1;" : "=r"(lo) : "f"(lf));
}

__device__ __forceinline__ void mma8(float* c, const uint32_t* a, const uint32_t* b) {
    asm volatile(
        "mma.sync.aligned.m16n8k8.row.col.f32.tf32.tf32.f32 "
        "{%0,%1,%2,%3}, {%4,%5,%6,%7}, {%8,%9}, {%0,%1,%2,%3};\n"
        : "+f"(c[0]), "+f"(c[1]), "+f"(c[2]), "+f"(c[3])
        : "r"(a[0]), "r"(a[1]), "r"(a[2]), "r"(a[3]), "r"(b[0]), "r"(b[1]));
}

__device__ __forceinline__ void cpa16(void* sptr, const void* gptr) {
    uint32_t s = (uint32_t)__cvta_generic_to_shared(sptr);
    asm volatile("cp.async.cg.shared.global [%0], [%1], 16;\n" :: "r"(s), "l"(gptr) : "memory");
}
#define CP_COMMIT() asm volatile("cp.async.commit_group;\n" ::: "memory")
#define CP_WAIT1()  asm volatile("cp.async.wait_group 1;\n" ::: "memory")

// ---------------- templated expert GEMM --------------------------------------------------
// BM=64 rows x OUTF cols. 8 warps = 4 over M x 2 over N. Each warp: one m16 tile,
// NF=4 n8 tiles (32 cols) per N-pass; NT=8 passes of BN=64 with double-buffered B.
// A raw row-major in smem (cp.async-gathered), split to tf32 hi/lo in-register.
// AREG: for small K, A fragments hoisted into registers once per block.
template <int K, bool AREG>
__device__ __forceinline__ void gemm_expert(
    int row0,
    const float* __restrict__ x,
    const float* __restrict__ we,    // w + e*OUTF*MAXF
    const float* __restrict__ be,    // bias + e*OUTF
    float* __restrict__ out,
    float* sm)
{
    constexpr int BN  = 64;
    constexpr int NT  = OUTF / BN;       // 8
    constexpr int NF  = 4;               // n8 tiles per warp
    constexpr int KS  = K / 8;
    constexpr int lds = K + 4;           // padded stride -> conflict-free scalar frag reads
    constexpr int kq  = K >> 2;          // float4 per row
    constexpr int KSR = AREG ? KS : 1;

    float* sA  = sm;                     // [BM][lds]
    float* sB0 = sm + BM * lds;          // [BN][lds] double-buffered
    float* sB1 = sB0 + BN * lds;

    const int tx = threadIdx.x;

    // ---- group 0: gathered A + B(0) ----
    #pragma unroll
    for (int i = tx; i < BM * kq; i += 256) {
        int r = i / kq, c = i % kq;
        int tok = g_rows[row0 + r];
        tok = tok < 0 ? 0 : tok;                       // padding row: dummy, discarded later
        cpa16(sA + r * lds + (c << 2), x + (size_t)tok * MAXF + (c << 2));
    }
    #pragma unroll
    for (int i = tx; i < BN * kq; i += 256) {
        int r = i / kq, c = i % kq;
        cpa16(sB0 + r * lds + (c << 2), we + (size_t)r * MAXF + (c << 2));
    }
    CP_COMMIT();
    // ---- group 1: B(1) ----
    #pragma unroll
    for (int i = tx; i < BN * kq; i += 256) {
        int r = i / kq, c = i % kq;
        cpa16(sB1 + r * lds + (c << 2), we + (size_t)(BN + r) * MAXF + (c << 2));
    }
    CP_COMMIT();

    const int warp = tx >> 5, lane = tx & 31;
    const int wm = warp & 3, wn = warp >> 2;           // 4 M-warps x 2 N-warps
    const int grp = lane >> 2, qid = lane & 3;

    const int t0 = g_rows[row0 + wm * 16 + grp];       // hoisted epilogue tokens
    const int t1 = g_rows[row0 + wm * 16 + grp + 8];
    const float* aBase = sA + (wm * 16 + grp) * lds + qid;

    uint32_t rah[KSR][4], ral[KSR][4];                 // A frags in regs (AREG path)

    for (int nt = 0; nt < NT; nt++) {
        CP_WAIT1();                                    // B(nt) (and A at nt=0) landed
        __syncthreads();
        const float* sB = (nt & 1) ? sB1 : sB0;

        if (AREG && nt == 0) {
            #pragma unroll
            for (int ks = 0; ks < KS; ks++) {
                const float* ap = aBase + ks * 8;
                split_tf32(ap[0],           rah[ks][0], ral[ks][0]);
                split_tf32(ap[8 * lds],     rah[ks][1], ral[ks][1]);
                split_tf32(ap[4],           rah[ks][2], ral[ks][2]);
                split_tf32(ap[8 * lds + 4], rah[ks][3], ral[ks][3]);
            }
        }

        float acc[NF][4] = {};

        #pragma unroll
        for (int ks = 0; ks < KS; ks++) {
            uint32_t ah[4], al[4];
            const uint32_t *pah, *pal;
            if (AREG) {
                pah = rah[ks]; pal = ral[ks];
            } else {
                const float* ap = aBase + ks * 8;
                split_tf32(ap[0],           ah[0], al[0]);
                split_tf32(ap[8 * lds],     ah[1], al[1]);
                split_tf32(ap[4],           ah[2], al[2]);
                split_tf32(ap[8 * lds + 4], ah[3], al[3]);
                pah = ah; pal = al;
            }
            #pragma unroll
            for (int nf = 0; nf < NF; nf++) {
                const float* bp = sB + (wn * 32 + nf * 8 + grp) * lds + ks * 8 + qid;
                uint32_t bh[2], bl[2];
                split_tf32(bp[0], bh[0], bl[0]);
                split_tf32(bp[4], bh[1], bl[1]);
                mma8(acc[nf], pah, bh);    // hi*hi
                mma8(acc[nf], pal, bh);    // lo*hi
                mma8(acc[nf], pah, bl);    // hi*lo
            }
        }

        // ---- scatter epilogue ----
        const int n0 = nt * BN + wn * 32;
        #pragma unroll
        for (int nf = 0; nf < NF; nf++) {
            int c = n0 + nf * 8 + (qid << 1);
            float2 bv = *(const float2*)(be + c);
            if (t0 >= 0) {
                float2 o = make_float2(acc[nf][0] + bv.x, acc[nf][1] + bv.y);
                *(float2*)(out + (size_t)t0 * OUTF + c) = o;
            }
            if (t1 >= 0) {
                float2 o = make_float2(acc[nf][2] + bv.x, acc[nf][3] + bv.y);
                *(float2*)(out + (size_t)t1 * OUTF + c) = o;
            }
        }

        __syncthreads();                               // buffer fully drained by all warps
        if (nt + 2 < NT) {
            float* sBn = (nt & 1) ? sB1 : sB0;
            #pragma unroll
            for (int i = tx; i < BN * kq; i += 256) {
                int r = i / kq, c = i % kq;
                cpa16(sBn + r * lds + (c << 2), we + (size_t)((nt + 2) * BN + r) * MAXF + (c << 2));
            }
        }
        CP_COMMIT();                                   // keep wait_group(1) invariant
    }
}

__global__ void __launch_bounds__(256, 2)
k_gemm(const float* __restrict__ x, const float* __restrict__ w,
       const float* __restrict__ bias, float* __restrict__ out) {
    extern __shared__ float sm[];
    // reversed order: heavy K=128 blocks (highest rows) scheduled FIRST
    const int total = g_offsets[NUM_E];
    const int row0  = total - (int)(blockIdx.x + 1) * BM;
    if (row0 < 0) return;

    int e = 0;
    #pragma unroll
    for (int i = 1; i < NUM_E; i++) e += (row0 >= g_offsets[i]);

    const float* we = w + (size_t)e * OUTF * MAXF;
    const float* be = bias + e * OUTF;

    switch (e) {
        case 0:  gemm_expert<  8, true >(row0, x, we, be, out, sm); break;
        case 1:  gemm_expert< 16, true >(row0, x, we, be, out, sm); break;
        case 2:  gemm_expert< 32, true >(row0, x, we, be, out, sm); break;
        case 3:  gemm_expert< 64, false>(row0, x, we, be, out, sm); break;
        default: gemm_expert<128, false>(row0, x, we, be, out, sm); break;
    }
}

// ---------------- launch ----------------
extern "C" void kernel_launch(void* const* d_in, const int* in_sizes, int n_in,
                              void* d_out, int out_size) {
    (void)in_sizes; (void)n_in; (void)out_size;
    const float* x    = (const float*)d_in[0];
    const int*   feat = (const int*)d_in[1];
    const float* w    = (const float*)d_in[2];
    const float* b    = (const float*)d_in[3];
    float*       out  = (float*)d_out;

    cudaFuncSetAttribute(k_gemm, cudaFuncAttributeMaxDynamicSharedMemorySize, SMEM_BYTES);

    k_count  <<<(NTOK + 255) / 256, 256>>>(feat);
    k_offsets<<<1, 256>>>();
    k_scatter<<<(NTOK + 255) / 256, 256>>>(feat);
    k_gemm   <<<MAX_MTILES, 256, SMEM_BYTES>>>(x, w, b, out);
}